// round 2
// baseline (speedup 1.0000x reference)
#include <cuda_runtime.h>
#include <cstdint>

// Problem constants (fixed by the reference)
#define BATCH   50000
#define KNEI    32
#define FDIM    256     // feature dim; 2F = 512 = GEMM K
#define NOUT    256

// Scratch for mean-aggregated neighbor features [BATCH, FDIM]
__device__ float g_xneigh[(size_t)BATCH * FDIM];

// 1 if neigh_idx buffer is int64, 0 if int32 (detected at runtime)
__device__ int g_idx_is64;

// ---------------------------------------------------------------------------
// Detector: for int64 indices in [0, 200000) every odd 32-bit word is 0.
// A random int32 index array has ~zero probability of 64 zero odd-words.
// ---------------------------------------------------------------------------
__global__ void detect_idx_kernel(const unsigned int* __restrict__ w) {
    int is64 = 1;
#pragma unroll 1
    for (int i = 1; i < 128; i += 2)
        if (w[i] != 0u) { is64 = 0; break; }
    g_idx_is64 = is64;
}

// ---------------------------------------------------------------------------
// Kernel A: gather + mean.  4 rows per block, 256 threads.
// thread t: row = blockIdx.x*4 + t/64, handles float4 column (t%64).
// Indices staged through smem so each row's 32 index loads happen once.
// ---------------------------------------------------------------------------
__global__ void gather_mean_kernel(const float4* __restrict__ feats4,
                                   const void* __restrict__ idx_raw) {
    const int rlocal = threadIdx.x >> 6;   // 0..3
    const int row    = blockIdx.x * 4 + rlocal;
    const int c      = threadIdx.x & 63;   // float4 column 0..63

    __shared__ int sidx[4][KNEI];
    if (threadIdx.x < 4 * KNEI) {
        const int r = threadIdx.x >> 5;
        const int k = threadIdx.x & 31;
        const long long flat = (long long)(blockIdx.x * 4 + r) * KNEI + k;
        int v;
        if (g_idx_is64) {
            v = (int)((const long long*)idx_raw)[flat];
        } else {
            v = ((const int*)idx_raw)[flat];
        }
        sidx[r][k] = v;
    }
    __syncthreads();

    float4 acc = make_float4(0.f, 0.f, 0.f, 0.f);
#pragma unroll
    for (int k = 0; k < KNEI; k++) {
        const float4 v = feats4[(long long)sidx[rlocal][k] * (FDIM / 4) + c];
        acc.x += v.x; acc.y += v.y; acc.z += v.z; acc.w += v.w;
    }
    const float s = 1.0f / (float)KNEI;
    acc.x *= s; acc.y *= s; acc.z *= s; acc.w *= s;
    reinterpret_cast<float4*>(g_xneigh)[(long long)row * (FDIM / 4) + c] = acc;
}

// ---------------------------------------------------------------------------
// Kernel B: fp32 SGEMM with logical-concat A and fused bias.
//   out[M, 256] = concat(x_self, x_neigh)[M, 512] @ W[512, 256] + bias
// Tiles: BM=128, BN=128, BK=16; 256 threads; 8x8 register tiles.
// A source pointer switches between x_self and g_xneigh per K-stage
// (each BK=16 stage lies entirely within one half since 256 % 16 == 0).
// ---------------------------------------------------------------------------
#define BM 128
#define BN 128
#define BK 16
#define TM 8
#define TN 8

__global__ __launch_bounds__(256, 2)
void sgemm_concat_kernel(const float* __restrict__ x_self,
                         const float* __restrict__ W,
                         const float* __restrict__ bias,
                         float* __restrict__ out,
                         int M) {
    __shared__ float As[BK][BM + 4];   // +4 pad: soften transposed-store conflicts
    __shared__ float Bs[BK][BN];

    const int bm  = blockIdx.x * BM;
    const int bn  = blockIdx.y * BN;
    const int tid = threadIdx.x;
    const int ty  = tid >> 4;          // 0..15
    const int tx  = tid & 15;          // 0..15

    float acc[TM][TN];
#pragma unroll
    for (int i = 0; i < TM; i++)
#pragma unroll
        for (int j = 0; j < TN; j++) acc[i][j] = 0.f;

    const float* __restrict__ xn = g_xneigh;

#pragma unroll 1
    for (int s = 0; s < 512 / BK; s++) {
        const int k0 = s * BK;
        // A stage source: first 256 of logical K from x_self, rest from x_neigh
        const float* __restrict__ Abase =
            (k0 < FDIM) ? (x_self + k0) : (xn + (k0 - FDIM));

        // ---- load A tile: 128 rows x 16 cols = 512 float4, 2 per thread ----
#pragma unroll
        for (int i = 0; i < 2; i++) {
            const int f  = tid + i * 256;     // 0..511
            const int r  = f >> 2;            // row in tile 0..127
            const int kq = (f & 3) * 4;       // k offset 0,4,8,12
            const int m  = bm + r;
            float4 v = make_float4(0.f, 0.f, 0.f, 0.f);
            if (m < M)
                v = *reinterpret_cast<const float4*>(Abase + (long long)m * FDIM + kq);
            As[kq + 0][r] = v.x;
            As[kq + 1][r] = v.y;
            As[kq + 2][r] = v.z;
            As[kq + 3][r] = v.w;
        }

        // ---- load B tile: 16 rows x 128 cols = 512 float4, 2 per thread ----
#pragma unroll
        for (int i = 0; i < 2; i++) {
            const int f  = tid + i * 256;     // 0..511
            const int r  = f >> 5;            // 0..15
            const int c4 = (f & 31) * 4;      // 0..124
            const float4 v = *reinterpret_cast<const float4*>(
                W + (long long)(k0 + r) * NOUT + bn + c4);
            *reinterpret_cast<float4*>(&Bs[r][c4]) = v;
        }

        __syncthreads();

        // ---- compute ----
#pragma unroll
        for (int kk = 0; kk < BK; kk++) {
            float a[TM], b[TN];
#pragma unroll
            for (int i = 0; i < TM; i++) a[i] = As[kk][ty * TM + i];
#pragma unroll
            for (int j = 0; j < TN; j++) b[j] = Bs[kk][tx * TN + j];
#pragma unroll
            for (int i = 0; i < TM; i++)
#pragma unroll
                for (int j = 0; j < TN; j++) acc[i][j] += a[i] * b[j];
        }

        __syncthreads();
    }

    // ---- epilogue: add bias, store ----
#pragma unroll
    for (int i = 0; i < TM; i++) {
        const int m = bm + ty * TM + i;
        if (m >= M) continue;
#pragma unroll
        for (int j = 0; j < TN; j += 4) {
            const int n = bn + tx * TN + j;
            float4 v;
            v.x = acc[i][j + 0] + bias[n + 0];
            v.y = acc[i][j + 1] + bias[n + 1];
            v.z = acc[i][j + 2] + bias[n + 2];
            v.w = acc[i][j + 3] + bias[n + 3];
            *reinterpret_cast<float4*>(out + (long long)m * NOUT + n) = v;
        }
    }
}

// ---------------------------------------------------------------------------
// Launch
// Inputs (metadata order): x_self[f32 B*F], feats[f32 N*F], neigh_idx[B*K],
//                          W[f32 512*256], b[f32 256]
// ---------------------------------------------------------------------------
extern "C" void kernel_launch(void* const* d_in, const int* in_sizes, int n_in,
                              void* d_out, int out_size) {
    const float*  x_self  = (const float*)d_in[0];
    const float4* feats4  = (const float4*)d_in[1];
    const void*   nidx    = d_in[2];
    const float*  W       = (const float*)d_in[3];
    const float*  bias    = (const float*)d_in[4];
    float*        out     = (float*)d_out;

    (void)in_sizes; (void)n_in; (void)out_size;

    // Detect int32 vs int64 index buffer (writes g_idx_is64)
    detect_idx_kernel<<<1, 1>>>((const unsigned int*)nidx);

    // Kernel A: 4 rows/block
    gather_mean_kernel<<<BATCH / 4, 256>>>(feats4, nidx);

    // Kernel B: SGEMM over logical concat
    dim3 grid((BATCH + BM - 1) / BM, NOUT / BN);
    sgemm_concat_kernel<<<grid, 256>>>(x_self, W, bias, out, BATCH);
}

// round 3
// speedup vs baseline: 1.7279x; 1.7279x over previous
#include <cuda_runtime.h>
#include <cstdint>

// Problem constants (fixed by the reference)
#define BATCH   50000
#define KNEI    32
#define FDIM    256     // feature dim; 2F = 512 = GEMM K
#define NOUT    256

// Scratch for mean-aggregated neighbor features [BATCH, FDIM]
__device__ float g_xneigh[(size_t)BATCH * FDIM];

// 1 if neigh_idx buffer is int64, 0 if int32 (detected at runtime)
__device__ int g_idx_is64;

// ---------------------------------------------------------------------------
// Detector: for int64 indices in [0, 200000) every odd 32-bit word is 0.
// A random int32 index array has ~zero probability of 64 zero odd-words.
// ---------------------------------------------------------------------------
__global__ void detect_idx_kernel(const unsigned int* __restrict__ w) {
    int is64 = 1;
#pragma unroll 1
    for (int i = 1; i < 128; i += 2)
        if (w[i] != 0u) { is64 = 0; break; }
    g_idx_is64 = is64;
}

// ---------------------------------------------------------------------------
// Kernel A: gather + mean.  4 rows per block, 256 threads.
// ---------------------------------------------------------------------------
__global__ void gather_mean_kernel(const float4* __restrict__ feats4,
                                   const void* __restrict__ idx_raw) {
    const int rlocal = threadIdx.x >> 6;   // 0..3
    const int row    = blockIdx.x * 4 + rlocal;
    const int c      = threadIdx.x & 63;   // float4 column 0..63

    __shared__ int sidx[4][KNEI];
    if (threadIdx.x < 4 * KNEI) {
        const int r = threadIdx.x >> 5;
        const int k = threadIdx.x & 31;
        const long long flat = (long long)(blockIdx.x * 4 + r) * KNEI + k;
        int v;
        if (g_idx_is64) v = (int)((const long long*)idx_raw)[flat];
        else            v = ((const int*)idx_raw)[flat];
        sidx[r][k] = v;
    }
    __syncthreads();

    float4 acc = make_float4(0.f, 0.f, 0.f, 0.f);
#pragma unroll
    for (int k = 0; k < KNEI; k++) {
        const float4 v = feats4[(long long)sidx[rlocal][k] * (FDIM / 4) + c];
        acc.x += v.x; acc.y += v.y; acc.z += v.z; acc.w += v.w;
    }
    const float s = 1.0f / (float)KNEI;
    acc.x *= s; acc.y *= s; acc.z *= s; acc.w *= s;
    reinterpret_cast<float4*>(g_xneigh)[(long long)row * (FDIM / 4) + c] = acc;
}

// ---------------------------------------------------------------------------
// Kernel B: TF32 tensor-core GEMM with logical-concat A and fused bias.
//   out[M, 256] = concat(x_self, x_neigh)[M, 512] @ W[512, 256] + bias
// BM=128, BN=128, BK=32; 256 threads = 8 warps (4 in M x 2 in N);
// warp tile 32x64 = 2x8 grid of mma.m16n8k8 tiles; fp32 accumulate.
// Smem strides chosen for conflict-free fragment loads:
//   A stride 36 words: bank = (4*row + col) % 32  -> injective over 8x4
//   B stride 136 words: bank = (8*k + n) % 32     -> injective over 4x8
// ---------------------------------------------------------------------------
#define BM 128
#define BN 128
#define BK 32
#define AS_STRIDE 36
#define BS_STRIDE 136

__device__ __forceinline__ unsigned f2tf32(float f) {
    unsigned u;
    asm("cvt.rna.tf32.f32 %0, %1;" : "=r"(u) : "f"(f));
    return u;
}

__device__ __forceinline__ void mma_tf32(float& d0, float& d1, float& d2, float& d3,
                                         unsigned a0, unsigned a1, unsigned a2, unsigned a3,
                                         unsigned b0, unsigned b1) {
    asm volatile(
        "mma.sync.aligned.m16n8k8.row.col.f32.tf32.tf32.f32 "
        "{%0,%1,%2,%3}, {%4,%5,%6,%7}, {%8,%9}, {%0,%1,%2,%3};"
        : "+f"(d0), "+f"(d1), "+f"(d2), "+f"(d3)
        : "r"(a0), "r"(a1), "r"(a2), "r"(a3), "r"(b0), "r"(b1));
}

__global__ __launch_bounds__(256, 2)
void gemm_tf32_concat_kernel(const float* __restrict__ x_self,
                             const float* __restrict__ W,
                             const float* __restrict__ bias,
                             float* __restrict__ out,
                             int M) {
    __shared__ unsigned As[BM * AS_STRIDE];   // 18432 B
    __shared__ unsigned Bs[BK * BS_STRIDE];   // 17408 B

    const int bm  = blockIdx.x * BM;
    const int bn  = blockIdx.y * BN;
    const int tid = threadIdx.x;

    const int warp = tid >> 5;
    const int lane = tid & 31;
    const int wm   = warp >> 1;        // 0..3 : warp row
    const int wn   = warp & 1;         // 0..1 : warp col
    const int gid  = lane >> 2;        // groupID 0..7
    const int tig  = lane & 3;         // thread-in-group 0..3

    float acc[2][8][4];
#pragma unroll
    for (int i = 0; i < 2; i++)
#pragma unroll
        for (int j = 0; j < 8; j++)
#pragma unroll
            for (int q = 0; q < 4; q++) acc[i][j][q] = 0.f;

    const float* __restrict__ xn = g_xneigh;

#pragma unroll 1
    for (int s = 0; s < 512 / BK; s++) {
        const int k0 = s * BK;
        // Each BK=32 stage lies entirely within one half (256 % 32 == 0)
        const float* __restrict__ Abase =
            (k0 < FDIM) ? (x_self + k0) : (xn + (k0 - FDIM));

        // ---- stage A tile: 128 x 32 = 1024 float4, 4 per thread ----
#pragma unroll
        for (int i = 0; i < 4; i++) {
            const int fi = tid + i * 256;          // 0..1023
            const int r  = fi >> 3;                // row 0..127
            const int c4 = (fi & 7) * 4;           // col 0,4,...,28
            const int m  = bm + r;
            float4 v = make_float4(0.f, 0.f, 0.f, 0.f);
            if (m < M)
                v = *reinterpret_cast<const float4*>(Abase + (long long)m * FDIM + c4);
            unsigned* dst = &As[r * AS_STRIDE + c4];
            dst[0] = f2tf32(v.x);
            dst[1] = f2tf32(v.y);
            dst[2] = f2tf32(v.z);
            dst[3] = f2tf32(v.w);
        }

        // ---- stage B tile: 32 x 128 = 1024 float4, 4 per thread ----
#pragma unroll
        for (int i = 0; i < 4; i++) {
            const int fi = tid + i * 256;          // 0..1023
            const int r  = fi >> 5;                // k row 0..31
            const int c4 = (fi & 31) * 4;          // col 0,4,...,124
            const float4 v = *reinterpret_cast<const float4*>(
                W + (long long)(k0 + r) * NOUT + bn + c4);
            unsigned* dst = &Bs[r * BS_STRIDE + c4];
            dst[0] = f2tf32(v.x);
            dst[1] = f2tf32(v.y);
            dst[2] = f2tf32(v.z);
            dst[3] = f2tf32(v.w);
        }

        __syncthreads();

        // ---- compute: 4 k-steps of 8 ----
#pragma unroll
        for (int ks = 0; ks < BK / 8; ks++) {
            const int kk = ks * 8;
            unsigned af[2][4];
#pragma unroll
            for (int mi = 0; mi < 2; mi++) {
                const int r0 = wm * 32 + mi * 16 + gid;
                af[mi][0] = As[(r0    ) * AS_STRIDE + kk + tig    ];
                af[mi][1] = As[(r0 + 8) * AS_STRIDE + kk + tig    ];
                af[mi][2] = As[(r0    ) * AS_STRIDE + kk + tig + 4];
                af[mi][3] = As[(r0 + 8) * AS_STRIDE + kk + tig + 4];
            }
            unsigned bf[8][2];
#pragma unroll
            for (int nj = 0; nj < 8; nj++) {
                const int cc = wn * 64 + nj * 8 + gid;
                bf[nj][0] = Bs[(kk + tig    ) * BS_STRIDE + cc];
                bf[nj][1] = Bs[(kk + tig + 4) * BS_STRIDE + cc];
            }
#pragma unroll
            for (int mi = 0; mi < 2; mi++)
#pragma unroll
                for (int nj = 0; nj < 8; nj++)
                    mma_tf32(acc[mi][nj][0], acc[mi][nj][1],
                             acc[mi][nj][2], acc[mi][nj][3],
                             af[mi][0], af[mi][1], af[mi][2], af[mi][3],
                             bf[nj][0], bf[nj][1]);
        }

        __syncthreads();
    }

    // ---- epilogue: bias + store (c0,c1 contiguous -> float2) ----
#pragma unroll
    for (int mi = 0; mi < 2; mi++) {
        const int m0 = bm + wm * 32 + mi * 16 + gid;
#pragma unroll
        for (int nj = 0; nj < 8; nj++) {
            const int n = bn + wn * 64 + nj * 8 + 2 * tig;
            const float b0 = bias[n];
            const float b1 = bias[n + 1];
            if (m0 < M) {
                float2 v = make_float2(acc[mi][nj][0] + b0, acc[mi][nj][1] + b1);
                *reinterpret_cast<float2*>(out + (long long)m0 * NOUT + n) = v;
            }
            if (m0 + 8 < M) {
                float2 v = make_float2(acc[mi][nj][2] + b0, acc[mi][nj][3] + b1);
                *reinterpret_cast<float2*>(out + (long long)(m0 + 8) * NOUT + n) = v;
            }
        }
    }
}

// ---------------------------------------------------------------------------
// Launch
// Inputs: x_self[f32 B*F], feats[f32 N*F], neigh_idx[B*K], W[f32 512*256], b[f32 256]
// ---------------------------------------------------------------------------
extern "C" void kernel_launch(void* const* d_in, const int* in_sizes, int n_in,
                              void* d_out, int out_size) {
    const float*  x_self = (const float*)d_in[0];
    const float4* feats4 = (const float4*)d_in[1];
    const void*   nidx   = d_in[2];
    const float*  W      = (const float*)d_in[3];
    const float*  bias   = (const float*)d_in[4];
    float*        out    = (float*)d_out;

    (void)in_sizes; (void)n_in; (void)out_size;

    detect_idx_kernel<<<1, 1>>>((const unsigned int*)nidx);

    gather_mean_kernel<<<BATCH / 4, 256>>>(feats4, nidx);

    dim3 grid((BATCH + BM - 1) / BM, NOUT / BN);
    gemm_tf32_concat_kernel<<<grid, 256>>>(x_self, W, bias, out, BATCH);
}

// round 4
// speedup vs baseline: 2.2629x; 1.3096x over previous
#include <cuda_runtime.h>
#include <cuda_fp16.h>
#include <cstdint>

// Problem constants (fixed by the reference)
#define BATCH   50000
#define KNEI    32
#define FDIM    256     // feature dim; 2F = 512 = GEMM K
#define NNODES  200000
#define NOUT    256

// fp16 copy of the feature table [NNODES, FDIM] (rebuilt every call)
__device__ __half g_feats_h[(size_t)NNODES * FDIM];
// fp16 mean-aggregated neighbor features [BATCH, FDIM]
__device__ __half g_xneigh_h[(size_t)BATCH * FDIM];

// ---------------------------------------------------------------------------
// Kernel 1: convert feats fp32 -> fp16.  Each thread: 8 floats.
// 51.2M elems / (256*8) = 25000 blocks.
// ---------------------------------------------------------------------------
__global__ void convert_feats_kernel(const float4* __restrict__ feats4) {
    const long long t = (long long)blockIdx.x * 256 + threadIdx.x;
    const float4 a = feats4[2 * t];
    const float4 b = feats4[2 * t + 1];
    __half2 o[4];
    o[0] = __floats2half2_rn(a.x, a.y);
    o[1] = __floats2half2_rn(a.z, a.w);
    o[2] = __floats2half2_rn(b.x, b.y);
    o[3] = __floats2half2_rn(b.z, b.w);
    *reinterpret_cast<uint4*>(g_feats_h + t * 8) = *reinterpret_cast<uint4*>(o);
}

// ---------------------------------------------------------------------------
// Kernel 2: gather + mean from fp16 table, fp32 accumulate, fp16 out.
// 8 rows per block (1 warp per row), 256 threads, 6250 blocks.
// Lane l covers 8 halves (16B) at column l*8; 32 k-iterations.
// Index dtype (int32 vs int64) detected per-block from the first 128
// 64-bit slots of the buffer: int64 indices < 200000 have all-zero hi words.
// ---------------------------------------------------------------------------
__global__ void gather_mean_kernel(const void* __restrict__ idx_raw) {
    const int tid  = threadIdx.x;
    const int warp = tid >> 5;
    const int lane = tid & 31;

    // --- dtype detection (uniform across grid; same 1KB read by all blocks) ---
    int hi_zero = 1;
    if (tid < 128) {
        const uint2 probe = reinterpret_cast<const uint2*>(idx_raw)[tid];
        hi_zero = (probe.y == 0u);
    }
    const int is64 = __syncthreads_and(hi_zero);

    // --- stage this block's 256 indices (8 rows x 32) ---
    __shared__ int sidx[256];
    const long long flat = (long long)blockIdx.x * 256 + tid;
    int v;
    if (is64) v = (int)reinterpret_cast<const long long*>(idx_raw)[flat];
    else      v = reinterpret_cast<const int*>(idx_raw)[flat];
    sidx[tid] = v;
    __syncthreads();

    const int row = blockIdx.x * 8 + warp;

    float acc[8];
#pragma unroll
    for (int j = 0; j < 8; j++) acc[j] = 0.f;

#pragma unroll
    for (int k = 0; k < KNEI; k++) {
        const long long node = sidx[warp * KNEI + k];
        const uint4 raw = *reinterpret_cast<const uint4*>(
            g_feats_h + node * FDIM + lane * 8);
        const __half2* h = reinterpret_cast<const __half2*>(&raw);
#pragma unroll
        for (int j = 0; j < 4; j++) {
            const float2 f = __half22float2(h[j]);
            acc[2 * j]     += f.x;
            acc[2 * j + 1] += f.y;
        }
    }
    const float s = 1.0f / (float)KNEI;
    __half2 o[4];
#pragma unroll
    for (int j = 0; j < 4; j++)
        o[j] = __floats2half2_rn(acc[2 * j] * s, acc[2 * j + 1] * s);
    *reinterpret_cast<uint4*>(g_xneigh_h + (long long)row * FDIM + lane * 8) =
        *reinterpret_cast<uint4*>(o);
}

// ---------------------------------------------------------------------------
// Kernel 3: TF32 tensor-core GEMM with logical-concat A and fused bias.
//   out[M, 256] = concat(x_self_f32, x_neigh_f16)[M, 512] @ W[512, 256] + bias
// BM=128, BN=128, BK=32; 256 threads = 8 warps (4 in M x 2 in N);
// warp tile 32x64 = 2x8 grid of mma.m16n8k8 tiles; fp32 accumulate.
// Smem strides chosen for conflict-free fragment loads:
//   A stride 36 words: bank = (4*row + col) % 32  -> injective over 8x4
//   B stride 136 words: bank = (8*k + n) % 32     -> injective over 4x8
// ---------------------------------------------------------------------------
#define BM 128
#define BN 128
#define BK 32
#define AS_STRIDE 36
#define BS_STRIDE 136

__device__ __forceinline__ unsigned f2tf32(float f) {
    unsigned u;
    asm("cvt.rna.tf32.f32 %0, %1;" : "=r"(u) : "f"(f));
    return u;
}

__device__ __forceinline__ void mma_tf32(float& d0, float& d1, float& d2, float& d3,
                                         unsigned a0, unsigned a1, unsigned a2, unsigned a3,
                                         unsigned b0, unsigned b1) {
    asm volatile(
        "mma.sync.aligned.m16n8k8.row.col.f32.tf32.tf32.f32 "
        "{%0,%1,%2,%3}, {%4,%5,%6,%7}, {%8,%9}, {%0,%1,%2,%3};"
        : "+f"(d0), "+f"(d1), "+f"(d2), "+f"(d3)
        : "r"(a0), "r"(a1), "r"(a2), "r"(a3), "r"(b0), "r"(b1));
}

__global__ __launch_bounds__(256, 2)
void gemm_tf32_concat_kernel(const float* __restrict__ x_self,
                             const float* __restrict__ W,
                             const float* __restrict__ bias,
                             float* __restrict__ out,
                             int M) {
    __shared__ unsigned As[BM * AS_STRIDE];   // 18432 B
    __shared__ unsigned Bs[BK * BS_STRIDE];   // 17408 B

    const int bm  = blockIdx.x * BM;
    const int bn  = blockIdx.y * BN;
    const int tid = threadIdx.x;

    const int warp = tid >> 5;
    const int lane = tid & 31;
    const int wm   = warp >> 1;        // 0..3 : warp row
    const int wn   = warp & 1;         // 0..1 : warp col
    const int gid  = lane >> 2;        // groupID 0..7
    const int tig  = lane & 3;         // thread-in-group 0..3

    float acc[2][8][4];
#pragma unroll
    for (int i = 0; i < 2; i++)
#pragma unroll
        for (int j = 0; j < 8; j++)
#pragma unroll
            for (int q = 0; q < 4; q++) acc[i][j][q] = 0.f;

    const __half* __restrict__ xn = g_xneigh_h;

#pragma unroll 1
    for (int s = 0; s < 512 / BK; s++) {
        const int k0 = s * BK;

        // ---- stage A tile: 128 x 32 ----
        if (k0 < FDIM) {
            // fp32 x_self path: 1024 float4, 4 per thread
#pragma unroll
            for (int i = 0; i < 4; i++) {
                const int fi = tid + i * 256;          // 0..1023
                const int r  = fi >> 3;                // row 0..127
                const int c4 = (fi & 7) * 4;           // col 0,4,...,28
                const int m  = bm + r;
                float4 v = make_float4(0.f, 0.f, 0.f, 0.f);
                if (m < M)
                    v = *reinterpret_cast<const float4*>(
                        x_self + (long long)m * FDIM + k0 + c4);
                unsigned* dst = &As[r * AS_STRIDE + c4];
                dst[0] = f2tf32(v.x);
                dst[1] = f2tf32(v.y);
                dst[2] = f2tf32(v.z);
                dst[3] = f2tf32(v.w);
            }
        } else {
            // fp16 x_neigh path: 512 uint4 (8 halves each), 2 per thread
            const int ksl = k0 - FDIM;
#pragma unroll
            for (int i = 0; i < 2; i++) {
                const int fi = tid + i * 256;          // 0..511
                const int r  = fi >> 2;                // row 0..127
                const int c8 = (fi & 3) * 8;           // col 0,8,16,24
                const int m  = bm + r;
                uint4 raw = make_uint4(0u, 0u, 0u, 0u);
                if (m < M)
                    raw = *reinterpret_cast<const uint4*>(
                        xn + (long long)m * FDIM + ksl + c8);
                const __half2* h = reinterpret_cast<const __half2*>(&raw);
                unsigned* dst = &As[r * AS_STRIDE + c8];
#pragma unroll
                for (int j = 0; j < 4; j++) {
                    const float2 f = __half22float2(h[j]);
                    dst[2 * j]     = f2tf32(f.x);
                    dst[2 * j + 1] = f2tf32(f.y);
                }
            }
        }

        // ---- stage B tile: 32 x 128 = 1024 float4, 4 per thread ----
#pragma unroll
        for (int i = 0; i < 4; i++) {
            const int fi = tid + i * 256;          // 0..1023
            const int r  = fi >> 5;                // k row 0..31
            const int c4 = (fi & 31) * 4;          // col 0,4,...,124
            const float4 v = *reinterpret_cast<const float4*>(
                W + (long long)(k0 + r) * NOUT + bn + c4);
            unsigned* dst = &Bs[r * BS_STRIDE + c4];
            dst[0] = f2tf32(v.x);
            dst[1] = f2tf32(v.y);
            dst[2] = f2tf32(v.z);
            dst[3] = f2tf32(v.w);
        }

        __syncthreads();

        // ---- compute: 4 k-steps of 8 ----
#pragma unroll
        for (int ks = 0; ks < BK / 8; ks++) {
            const int kk = ks * 8;
            unsigned af[2][4];
#pragma unroll
            for (int mi = 0; mi < 2; mi++) {
                const int r0 = wm * 32 + mi * 16 + gid;
                af[mi][0] = As[(r0    ) * AS_STRIDE + kk + tig    ];
                af[mi][1] = As[(r0 + 8) * AS_STRIDE + kk + tig    ];
                af[mi][2] = As[(r0    ) * AS_STRIDE + kk + tig + 4];
                af[mi][3] = As[(r0 + 8) * AS_STRIDE + kk + tig + 4];
            }
            unsigned bf[8][2];
#pragma unroll
            for (int nj = 0; nj < 8; nj++) {
                const int cc = wn * 64 + nj * 8 + gid;
                bf[nj][0] = Bs[(kk + tig    ) * BS_STRIDE + cc];
                bf[nj][1] = Bs[(kk + tig + 4) * BS_STRIDE + cc];
            }
#pragma unroll
            for (int mi = 0; mi < 2; mi++)
#pragma unroll
                for (int nj = 0; nj < 8; nj++)
                    mma_tf32(acc[mi][nj][0], acc[mi][nj][1],
                             acc[mi][nj][2], acc[mi][nj][3],
                             af[mi][0], af[mi][1], af[mi][2], af[mi][3],
                             bf[nj][0], bf[nj][1]);
        }

        __syncthreads();
    }

    // ---- epilogue: bias + store (c0,c1 contiguous -> float2) ----
#pragma unroll
    for (int mi = 0; mi < 2; mi++) {
        const int m0 = bm + wm * 32 + mi * 16 + gid;
#pragma unroll
        for (int nj = 0; nj < 8; nj++) {
            const int n = bn + wn * 64 + nj * 8 + 2 * tig;
            const float b0 = bias[n];
            const float b1 = bias[n + 1];
            if (m0 < M) {
                float2 v = make_float2(acc[mi][nj][0] + b0, acc[mi][nj][1] + b1);
                *reinterpret_cast<float2*>(out + (long long)m0 * NOUT + n) = v;
            }
            if (m0 + 8 < M) {
                float2 v = make_float2(acc[mi][nj][2] + b0, acc[mi][nj][3] + b1);
                *reinterpret_cast<float2*>(out + (long long)(m0 + 8) * NOUT + n) = v;
            }
        }
    }
}

// ---------------------------------------------------------------------------
// Launch
// Inputs: x_self[f32 B*F], feats[f32 N*F], neigh_idx[B*K], W[f32 512*256], b[f32 256]
// ---------------------------------------------------------------------------
extern "C" void kernel_launch(void* const* d_in, const int* in_sizes, int n_in,
                              void* d_out, int out_size) {
    const float*  x_self = (const float*)d_in[0];
    const float4* feats4 = (const float4*)d_in[1];
    const void*   nidx   = d_in[2];
    const float*  W      = (const float*)d_in[3];
    const float*  bias   = (const float*)d_in[4];
    float*        out    = (float*)d_out;

    (void)in_sizes; (void)n_in; (void)out_size;

    // 1) fp32 -> fp16 feature table (51.2M elems, 8 per thread)
    convert_feats_kernel<<<(NNODES * FDIM) / (256 * 8), 256>>>(feats4);

    // 2) gather + mean (8 rows per block)
    gather_mean_kernel<<<BATCH / 8, 256>>>(nidx);

    // 3) TF32 GEMM over logical concat
    dim3 grid((BATCH + BM - 1) / BM, NOUT / BN);
    gemm_tf32_concat_kernel<<<grid, 256>>>(x_self, W, bias, out, BATCH);
}

// round 5
// speedup vs baseline: 2.4520x; 1.0835x over previous
#include <cuda_runtime.h>
#include <cuda_fp16.h>
#include <cstdint>

// Problem constants (fixed by the reference)
#define BATCH   50000
#define KNEI    32
#define FDIM    256     // feature dim; 2F = 512 = GEMM K
#define NNODES  200000
#define NOUT    256

// fp16 copy of the feature table [NNODES, FDIM] (rebuilt every call)
__device__ __half g_feats_h[(size_t)NNODES * FDIM];
// fp16 mean-aggregated neighbor features [BATCH, FDIM]
__device__ __half g_xneigh_h[(size_t)BATCH * FDIM];
// fp16 transposed weights: W_t[n][k], n in [0,256), k in [0,512)
__device__ __half g_W_t[(size_t)NOUT * 2 * FDIM];

// ---------------------------------------------------------------------------
// Kernel 1: convert feats fp32 -> fp16.  Each thread: 8 floats.
// ---------------------------------------------------------------------------
__global__ void convert_feats_kernel(const float4* __restrict__ feats4) {
    const long long t = (long long)blockIdx.x * 256 + threadIdx.x;
    const float4 a = feats4[2 * t];
    const float4 b = feats4[2 * t + 1];
    __half2 o[4];
    o[0] = __floats2half2_rn(a.x, a.y);
    o[1] = __floats2half2_rn(a.z, a.w);
    o[2] = __floats2half2_rn(b.x, b.y);
    o[3] = __floats2half2_rn(b.z, b.w);
    *reinterpret_cast<uint4*>(g_feats_h + t * 8) = *reinterpret_cast<uint4*>(o);
}

// ---------------------------------------------------------------------------
// Kernel 1b: W [512k][256n] fp32 -> W_t [256n][512k] fp16 (tiled transpose)
// grid (16, 8), block 256 (32x8).
// ---------------------------------------------------------------------------
__global__ void convert_W_kernel(const float* __restrict__ W) {
    __shared__ float tile[32][33];
    const int tx = threadIdx.x & 31;
    const int ty = threadIdx.x >> 5;        // 0..7
    const int k0 = blockIdx.x * 32;
    const int n0 = blockIdx.y * 32;
#pragma unroll
    for (int j = 0; j < 4; j++)
        tile[ty + j * 8][tx] = W[(long long)(k0 + ty + j * 8) * NOUT + n0 + tx];
    __syncthreads();
#pragma unroll
    for (int j = 0; j < 4; j++) {
        const int n = ty + j * 8;
        g_W_t[(long long)(n0 + n) * (2 * FDIM) + k0 + tx] =
            __float2half(tile[tx][n]);
    }
}

// ---------------------------------------------------------------------------
// Kernel 2: gather + mean from fp16 table, fp32 accumulate, fp16 out.
// 8 rows per block (1 warp per row), 256 threads.
// Index dtype (int32 vs int64) detected per-block from the first 128
// 64-bit slots: int64 indices < 200000 have all-zero hi words.
// ---------------------------------------------------------------------------
__global__ void gather_mean_kernel(const void* __restrict__ idx_raw) {
    const int tid  = threadIdx.x;
    const int warp = tid >> 5;
    const int lane = tid & 31;

    int hi_zero = 1;
    if (tid < 128) {
        const uint2 probe = reinterpret_cast<const uint2*>(idx_raw)[tid];
        hi_zero = (probe.y == 0u);
    }
    const int is64 = __syncthreads_and(hi_zero);

    __shared__ int sidx[256];
    const long long flat = (long long)blockIdx.x * 256 + tid;
    int v;
    if (is64) v = (int)reinterpret_cast<const long long*>(idx_raw)[flat];
    else      v = reinterpret_cast<const int*>(idx_raw)[flat];
    sidx[tid] = v;
    __syncthreads();

    const int row = blockIdx.x * 8 + warp;

    float acc[8];
#pragma unroll
    for (int j = 0; j < 8; j++) acc[j] = 0.f;

#pragma unroll
    for (int k = 0; k < KNEI; k++) {
        const long long node = sidx[warp * KNEI + k];
        const uint4 raw = *reinterpret_cast<const uint4*>(
            g_feats_h + node * FDIM + lane * 8);
        const __half2* h = reinterpret_cast<const __half2*>(&raw);
#pragma unroll
        for (int j = 0; j < 4; j++) {
            const float2 f = __half22float2(h[j]);
            acc[2 * j]     += f.x;
            acc[2 * j + 1] += f.y;
        }
    }
    const float s = 1.0f / (float)KNEI;
    __half2 o[4];
#pragma unroll
    for (int j = 0; j < 4; j++)
        o[j] = __floats2half2_rn(acc[2 * j] * s, acc[2 * j + 1] * s);
    *reinterpret_cast<uint4*>(g_xneigh_h + (long long)row * FDIM + lane * 8) =
        *reinterpret_cast<uint4*>(o);
}

// ---------------------------------------------------------------------------
// Kernel 3: fp16 tensor-core GEMM (mma.m16n8k16, fp32 accum), logical-concat
// A, fused bias.  out[M,256] = concat(x_self, x_neigh)[M,512] @ W + b
// BM=128, BN=128, BK=32; 8 warps (4 in M x 2 in N); warp tile 32x64.
// A smem [128][BK] halves, row stride 40 halves (80B): ldmatrix phases hit
// banks {0,20,8,28,16,4,24,12}*4 -> conflict-free.
// B smem transposed [n][k], same stride: half2 loads conflict-free
// (bank = 20n + tig pattern covers all 32 banks).
// ---------------------------------------------------------------------------
#define BM 128
#define BN 128
#define BK 32
#define ASTR 40   // halves

__device__ __forceinline__ void mma_f16(float& d0, float& d1, float& d2, float& d3,
                                        unsigned a0, unsigned a1, unsigned a2, unsigned a3,
                                        unsigned b0, unsigned b1) {
    asm volatile(
        "mma.sync.aligned.m16n8k16.row.col.f32.f16.f16.f32 "
        "{%0,%1,%2,%3}, {%4,%5,%6,%7}, {%8,%9}, {%0,%1,%2,%3};"
        : "+f"(d0), "+f"(d1), "+f"(d2), "+f"(d3)
        : "r"(a0), "r"(a1), "r"(a2), "r"(a3), "r"(b0), "r"(b1));
}

__device__ __forceinline__ void ldmatrix_x4(unsigned& r0, unsigned& r1,
                                            unsigned& r2, unsigned& r3,
                                            unsigned saddr) {
    asm volatile("ldmatrix.sync.aligned.m8n8.x4.shared.b16 {%0,%1,%2,%3}, [%4];"
                 : "=r"(r0), "=r"(r1), "=r"(r2), "=r"(r3) : "r"(saddr));
}

__global__ __launch_bounds__(256)
void gemm_f16_concat_kernel(const float* __restrict__ x_self,
                            const float* __restrict__ bias,
                            float* __restrict__ out,
                            int M) {
    __shared__ __align__(16) __half As[BM * ASTR];
    __shared__ __align__(16) __half Bs[BN * ASTR];

    const int bm  = blockIdx.x * BM;
    const int bn  = blockIdx.y * BN;
    const int tid = threadIdx.x;

    const int warp = tid >> 5;
    const int lane = tid & 31;
    const int wm   = warp >> 1;        // 0..3
    const int wn   = warp & 1;         // 0..1
    const int gid  = lane >> 2;        // 0..7
    const int tig  = lane & 3;         // 0..3

    float acc[2][8][4];
#pragma unroll
    for (int i = 0; i < 2; i++)
#pragma unroll
        for (int j = 0; j < 8; j++)
#pragma unroll
            for (int q = 0; q < 4; q++) acc[i][j][q] = 0.f;

    const __half* __restrict__ xn = g_xneigh_h;
    const __half* __restrict__ Wt = g_W_t;

    // ldmatrix lane addressing precompute (A fragments)
    const int lm_tile = lane >> 3;            // 0..3
    const int lm_row  = (lane & 7) + (lm_tile & 1) * 8;   // row within 16
    const int lm_koff = (lm_tile >> 1) * 8;               // 0 or 8 halves

    const unsigned as_base = (unsigned)__cvta_generic_to_shared(As);
    const unsigned bs_base = (unsigned)__cvta_generic_to_shared(Bs);

#pragma unroll 1
    for (int s = 0; s < 512 / BK; s++) {
        const int k0 = s * BK;

        // ---- stage A tile: 128 rows x 32 halves ----
        if (k0 < FDIM) {
            // fp32 x_self: 1024 float4, 4/thread -> convert to half
#pragma unroll
            for (int i = 0; i < 4; i++) {
                const int fi = tid + i * 256;      // 0..1023
                const int r  = fi >> 3;            // 0..127
                const int cf = (fi & 7) * 4;       // float col 0..28
                const int m  = bm + r;
                float4 v = make_float4(0.f, 0.f, 0.f, 0.f);
                if (m < M)
                    v = *reinterpret_cast<const float4*>(
                        x_self + (long long)m * FDIM + k0 + cf);
                __half2 h[2];
                h[0] = __floats2half2_rn(v.x, v.y);
                h[1] = __floats2half2_rn(v.z, v.w);
                *reinterpret_cast<uint2*>(&As[r * ASTR + cf]) =
                    *reinterpret_cast<uint2*>(h);
            }
        } else {
            // fp16 x_neigh: 512 uint4, 2/thread, pass-through
            const int ksl = k0 - FDIM;
#pragma unroll
            for (int i = 0; i < 2; i++) {
                const int fi = tid + i * 256;      // 0..511
                const int r  = fi >> 2;            // 0..127
                const int c8 = (fi & 3) * 8;       // 0,8,16,24
                const int m  = bm + r;
                uint4 raw = make_uint4(0u, 0u, 0u, 0u);
                if (m < M)
                    raw = *reinterpret_cast<const uint4*>(
                        xn + (long long)m * FDIM + ksl + c8);
                *reinterpret_cast<uint4*>(&As[r * ASTR + c8]) = raw;
            }
        }

        // ---- stage B tile (transposed): 128 n-rows x 32 k-halves ----
#pragma unroll
        for (int i = 0; i < 2; i++) {
            const int fi = tid + i * 256;          // 0..511
            const int n  = fi >> 2;                // 0..127
            const int c8 = (fi & 3) * 8;           // 0,8,16,24
            const uint4 raw = *reinterpret_cast<const uint4*>(
                Wt + (long long)(bn + n) * (2 * FDIM) + k0 + c8);
            *reinterpret_cast<uint4*>(&Bs[n * ASTR + c8]) = raw;
        }

        __syncthreads();

        // ---- compute: 2 k-steps of 16 ----
#pragma unroll
        for (int ks = 0; ks < 2; ks++) {
            const int kk = ks * 16;
            unsigned af[2][4];
#pragma unroll
            for (int mi = 0; mi < 2; mi++) {
                const int r = wm * 32 + mi * 16 + lm_row;
                const unsigned sa = as_base + (r * ASTR + kk + lm_koff) * 2;
                ldmatrix_x4(af[mi][0], af[mi][1], af[mi][2], af[mi][3], sa);
            }
#pragma unroll
            for (int nj = 0; nj < 8; nj++) {
                const int n = wn * 64 + nj * 8 + gid;
                const unsigned b0 = *reinterpret_cast<const unsigned*>(
                    &Bs[n * ASTR + kk + 2 * tig]);
                const unsigned b1 = *reinterpret_cast<const unsigned*>(
                    &Bs[n * ASTR + kk + 8 + 2 * tig]);
                mma_f16(acc[0][nj][0], acc[0][nj][1], acc[0][nj][2], acc[0][nj][3],
                        af[0][0], af[0][1], af[0][2], af[0][3], b0, b1);
                mma_f16(acc[1][nj][0], acc[1][nj][1], acc[1][nj][2], acc[1][nj][3],
                        af[1][0], af[1][1], af[1][2], af[1][3], b0, b1);
            }
        }

        __syncthreads();
    }

    // ---- epilogue: bias + store (c0,c1 contiguous -> float2) ----
#pragma unroll
    for (int mi = 0; mi < 2; mi++) {
        const int m0 = bm + wm * 32 + mi * 16 + gid;
#pragma unroll
        for (int nj = 0; nj < 8; nj++) {
            const int n = bn + wn * 64 + nj * 8 + 2 * tig;
            const float b0 = bias[n];
            const float b1 = bias[n + 1];
            if (m0 < M) {
                float2 v = make_float2(acc[mi][nj][0] + b0, acc[mi][nj][1] + b1);
                *reinterpret_cast<float2*>(out + (long long)m0 * NOUT + n) = v;
            }
            if (m0 + 8 < M) {
                float2 v = make_float2(acc[mi][nj][2] + b0, acc[mi][nj][3] + b1);
                *reinterpret_cast<float2*>(out + (long long)(m0 + 8) * NOUT + n) = v;
            }
        }
    }
}

// ---------------------------------------------------------------------------
// Launch
// Inputs: x_self[f32 B*F], feats[f32 N*F], neigh_idx[B*K], W[f32 512*256], b[f32 256]
// ---------------------------------------------------------------------------
extern "C" void kernel_launch(void* const* d_in, const int* in_sizes, int n_in,
                              void* d_out, int out_size) {
    const float*  x_self = (const float*)d_in[0];
    const float4* feats4 = (const float4*)d_in[1];
    const void*   nidx   = d_in[2];
    const float*  W      = (const float*)d_in[3];
    const float*  bias   = (const float*)d_in[4];
    float*        out    = (float*)d_out;

    (void)in_sizes; (void)n_in; (void)out_size;

    // 1) fp32 -> fp16 feature table
    convert_feats_kernel<<<(NNODES * FDIM) / (256 * 8), 256>>>(feats4);

    // 1b) W -> W_t fp16 (transposed)
    {
        dim3 g(2 * FDIM / 32, NOUT / 32);
        convert_W_kernel<<<g, 256>>>(W);
    }

    // 2) gather + mean
    gather_mean_kernel<<<BATCH / 8, 256>>>(nidx);

    // 3) fp16 tensor-core GEMM over logical concat
    dim3 grid((BATCH + BM - 1) / BM, NOUT / BN);
    gemm_f16_concat_kernel<<<grid, 256>>>(x_self, bias, out, BATCH);
}

// round 6
// speedup vs baseline: 2.4742x; 1.0091x over previous
#include <cuda_runtime.h>
#include <cuda_fp16.h>
#include <cstdint>

// Problem constants (fixed by the reference)
#define BATCH   50000
#define KNEI    32
#define FDIM    256     // feature dim; 2F = 512 = GEMM K
#define NNODES  200000
#define NOUT    256

// fp16 copy of the feature table [NNODES, FDIM] (rebuilt every call)
__device__ __half g_feats_h[(size_t)NNODES * FDIM];
// fp16 concatenated GEMM A matrix: [BATCH][512] = [x_self_f16 | x_neigh_f16]
__device__ __half g_h[(size_t)BATCH * 2 * FDIM];
// fp16 transposed weights: W_t[n][k], n in [0,256), k in [0,512)
__device__ __half g_W_t[(size_t)NOUT * 2 * FDIM];

#define FEATS_BLOCKS ((NNODES * FDIM) / (256 * 8))   // 25000
#define XSELF_BLOCKS ((BATCH * FDIM) / (256 * 8))    // 6250

// ---------------------------------------------------------------------------
// Kernel 1: convert feats fp32 -> fp16 table AND x_self fp32 -> fp16 into the
// left half of g_h.  One launch, both pure HBM streaming.
// ---------------------------------------------------------------------------
__global__ void convert_kernel(const float4* __restrict__ feats4,
                               const float4* __restrict__ xself4) {
    if (blockIdx.x < FEATS_BLOCKS) {
        const long long t = (long long)blockIdx.x * 256 + threadIdx.x;
        const float4 a = feats4[2 * t];
        const float4 b = feats4[2 * t + 1];
        __half2 o[4];
        o[0] = __floats2half2_rn(a.x, a.y);
        o[1] = __floats2half2_rn(a.z, a.w);
        o[2] = __floats2half2_rn(b.x, b.y);
        o[3] = __floats2half2_rn(b.z, b.w);
        *reinterpret_cast<uint4*>(g_feats_h + t * 8) = *reinterpret_cast<uint4*>(o);
    } else {
        const long long e = (long long)(blockIdx.x - FEATS_BLOCKS) * 256 + threadIdx.x;
        const float4 a = xself4[2 * e];
        const float4 b = xself4[2 * e + 1];
        __half2 o[4];
        o[0] = __floats2half2_rn(a.x, a.y);
        o[1] = __floats2half2_rn(a.z, a.w);
        o[2] = __floats2half2_rn(b.x, b.y);
        o[3] = __floats2half2_rn(b.z, b.w);
        const long long row = e / 32;          // 32 * 8 halves = 256 per row
        const long long col = (e % 32) * 8;
        *reinterpret_cast<uint4*>(g_h + row * (2 * FDIM) + col) =
            *reinterpret_cast<uint4*>(o);
    }
}

// ---------------------------------------------------------------------------
// Kernel 1b: W [512k][256n] fp32 -> W_t [256n][512k] fp16 (tiled transpose)
// ---------------------------------------------------------------------------
__global__ void convert_W_kernel(const float* __restrict__ W) {
    __shared__ float tile[32][33];
    const int tx = threadIdx.x & 31;
    const int ty = threadIdx.x >> 5;        // 0..7
    const int k0 = blockIdx.x * 32;
    const int n0 = blockIdx.y * 32;
#pragma unroll
    for (int j = 0; j < 4; j++)
        tile[ty + j * 8][tx] = W[(long long)(k0 + ty + j * 8) * NOUT + n0 + tx];
    __syncthreads();
#pragma unroll
    for (int j = 0; j < 4; j++) {
        const int n = ty + j * 8;
        g_W_t[(long long)(n0 + n) * (2 * FDIM) + k0 + tx] =
            __float2half(tile[tx][n]);
    }
}

// ---------------------------------------------------------------------------
// Kernel 2: gather + mean from fp16 table, fp32 accumulate, fp16 out into
// the right half (cols 256..511) of g_h.  8 rows/block, 1 warp per row.
// ---------------------------------------------------------------------------
__global__ void gather_mean_kernel(const void* __restrict__ idx_raw) {
    const int tid  = threadIdx.x;
    const int warp = tid >> 5;
    const int lane = tid & 31;

    int hi_zero = 1;
    if (tid < 128) {
        const uint2 probe = reinterpret_cast<const uint2*>(idx_raw)[tid];
        hi_zero = (probe.y == 0u);
    }
    const int is64 = __syncthreads_and(hi_zero);

    __shared__ int sidx[256];
    const long long flat = (long long)blockIdx.x * 256 + tid;
    int v;
    if (is64) v = (int)reinterpret_cast<const long long*>(idx_raw)[flat];
    else      v = reinterpret_cast<const int*>(idx_raw)[flat];
    sidx[tid] = v;
    __syncthreads();

    const int row = blockIdx.x * 8 + warp;

    float acc[8];
#pragma unroll
    for (int j = 0; j < 8; j++) acc[j] = 0.f;

#pragma unroll
    for (int k = 0; k < KNEI; k++) {
        const long long node = sidx[warp * KNEI + k];
        const uint4 raw = *reinterpret_cast<const uint4*>(
            g_feats_h + node * FDIM + lane * 8);
        const __half2* h = reinterpret_cast<const __half2*>(&raw);
#pragma unroll
        for (int j = 0; j < 4; j++) {
            const float2 f = __half22float2(h[j]);
            acc[2 * j]     += f.x;
            acc[2 * j + 1] += f.y;
        }
    }
    const float s = 1.0f / (float)KNEI;
    __half2 o[4];
#pragma unroll
    for (int j = 0; j < 4; j++)
        o[j] = __floats2half2_rn(acc[2 * j] * s, acc[2 * j + 1] * s);
    *reinterpret_cast<uint4*>(g_h + (long long)row * (2 * FDIM) + FDIM + lane * 8) =
        *reinterpret_cast<uint4*>(o);
}

// ---------------------------------------------------------------------------
// Kernel 3: fp16 tensor-core GEMM, 3-stage cp.async pipeline.
//   out[M,256] = g_h[M,512] @ W_t^T + bias
// BM=128, BN=128, BK=32, STAGES=3 (48KB smem).  8 warps: 4 in M x 2 in N,
// warp tile 32x64.  A and B tiles [128][32] halves with XOR-16B swizzle
// (off ^ ((off>>7 & 7) << 4)): conflict-free for ldmatrix and cp.async.
// ---------------------------------------------------------------------------
#define BM 128
#define BN 128
#define BK 32
#define STAGES 3
#define TILE_B (BM * BK * 2)     // 8192 bytes per tile

__device__ __forceinline__ unsigned swz(unsigned off) {
    return off ^ (((off >> 7) & 7u) << 4);
}

__device__ __forceinline__ void mma_f16(float& d0, float& d1, float& d2, float& d3,
                                        unsigned a0, unsigned a1, unsigned a2, unsigned a3,
                                        unsigned b0, unsigned b1) {
    asm volatile(
        "mma.sync.aligned.m16n8k16.row.col.f32.f16.f16.f32 "
        "{%0,%1,%2,%3}, {%4,%5,%6,%7}, {%8,%9}, {%0,%1,%2,%3};"
        : "+f"(d0), "+f"(d1), "+f"(d2), "+f"(d3)
        : "r"(a0), "r"(a1), "r"(a2), "r"(a3), "r"(b0), "r"(b1));
}

__device__ __forceinline__ void ldmatrix_x4(unsigned& r0, unsigned& r1,
                                            unsigned& r2, unsigned& r3,
                                            unsigned saddr) {
    asm volatile("ldmatrix.sync.aligned.m8n8.x4.shared.b16 {%0,%1,%2,%3}, [%4];"
                 : "=r"(r0), "=r"(r1), "=r"(r2), "=r"(r3) : "r"(saddr));
}

__device__ __forceinline__ void cp_async16(unsigned dst, const void* src, int src_sz) {
    asm volatile("cp.async.cg.shared.global [%0], [%1], 16, %2;\n"
                 :: "r"(dst), "l"(src), "r"(src_sz));
}
__device__ __forceinline__ void cp_commit() {
    asm volatile("cp.async.commit_group;\n");
}
template <int N>
__device__ __forceinline__ void cp_wait() {
    asm volatile("cp.async.wait_group %0;\n" :: "n"(N));
}

__global__ __launch_bounds__(256, 2)
void gemm_f16_pipe_kernel(const float* __restrict__ bias,
                          float* __restrict__ out,
                          int M) {
    __shared__ __align__(16) char smem[STAGES * 2 * TILE_B];
    // stage st: A at smem + st*2*TILE_B, B at +TILE_B

    const int bm  = blockIdx.x * BM;
    const int bn  = blockIdx.y * BN;
    const int tid = threadIdx.x;

    const int warp = tid >> 5;
    const int lane = tid & 31;
    const int wm   = warp >> 1;        // 0..3
    const int wn   = warp & 1;         // 0..1
    const int gid  = lane >> 2;        // 0..7
    const int tig  = lane & 3;         // 0..3

    const unsigned sbase = (unsigned)__cvta_generic_to_shared(smem);

    const __half* __restrict__ A  = g_h;
    const __half* __restrict__ Wt = g_W_t;

    // cp.async per-thread mapping: 2 granules for A, 2 for B per stage.
    // fi = tid + i*256; r = fi & 127 (fast), c16 = fi >> 7 (granule col 0..3)
    const int r_ld  = tid & 127;
    // A fragment ldmatrix lane addressing
    const int lm_tile = lane >> 3;
    const int lm_row  = (lane & 7) + (lm_tile & 1) * 8;
    const int lm_koff = (lm_tile >> 1) * 8;
    // B fragment ldmatrix lane addressing (non-trans over [n][k] rows)
    const int bn_row  = ((lane >> 4) & 1) * 8 + (lane & 7);
    const int bk_add  = ((lane >> 3) & 1) * 8;

    float acc[2][8][4];
#pragma unroll
    for (int i = 0; i < 2; i++)
#pragma unroll
        for (int j = 0; j < 8; j++)
#pragma unroll
            for (int q = 0; q < 4; q++) acc[i][j][q] = 0.f;

    // ---- stage issuer (lambda-less) ----
    // stage s covers k0 = s*BK
#define ISSUE_STAGE(s, buf)                                                     \
    {                                                                           \
        const int k0 = (s) * BK;                                                \
        const unsigned abase = sbase + (buf) * 2 * TILE_B;                      \
        const unsigned bbase = abase + TILE_B;                                  \
        _Pragma("unroll")                                                       \
        for (int i = 0; i < 2; i++) {                                           \
            const int fi  = tid + i * 256;                                      \
            const int r   = fi & 127;                                           \
            const int c16 = fi >> 7;                                            \
            const unsigned soff = swz((unsigned)(r * 64 + c16 * 16));           \
            const int m = bm + r;                                               \
            const __half* srcA = A + (long long)m * (2 * FDIM) + k0 + c16 * 8;  \
            cp_async16(abase + soff, srcA, (m < M) ? 16 : 0);                   \
            const __half* srcB = Wt + (long long)(bn + r) * (2 * FDIM) + k0 + c16 * 8; \
            cp_async16(bbase + soff, srcB, 16);                                 \
        }                                                                       \
        cp_commit();                                                            \
    }

    // ---- prologue: issue stages 0,1 ----
    ISSUE_STAGE(0, 0)
    ISSUE_STAGE(1, 1)

    const int NSTAGE = (2 * FDIM) / BK;   // 16

#pragma unroll 1
    for (int s = 0; s < NSTAGE; s++) {
        if (s < NSTAGE - 2) cp_wait<1>();
        else                cp_wait<0>();
        __syncthreads();

        // issue stage s+2 into buffer (s+2)%3 (all warps past compute(s-1))
        if (s + 2 < NSTAGE) {
            const int nb = (s + 2) % STAGES;
            ISSUE_STAGE(s + 2, nb)
        }

        // compute stage s from buffer s%3
        const unsigned abase = sbase + (s % STAGES) * 2 * TILE_B;
        const unsigned bbase = abase + TILE_B;

#pragma unroll
        for (int ks = 0; ks < 2; ks++) {
            const int kk = ks * 16;
            unsigned af[2][4];
#pragma unroll
            for (int mi = 0; mi < 2; mi++) {
                const int r = wm * 32 + mi * 16 + lm_row;
                const unsigned sa = abase + swz((unsigned)(r * 64 + (kk + lm_koff) * 2));
                ldmatrix_x4(af[mi][0], af[mi][1], af[mi][2], af[mi][3], sa);
            }
            unsigned bf[8][2];
#pragma unroll
            for (int nj2 = 0; nj2 < 4; nj2++) {
                const int n = wn * 64 + nj2 * 16 + bn_row;
                const unsigned sb = bbase + swz((unsigned)(n * 64 + (kk + bk_add) * 2));
                unsigned r0, r1, r2, r3;
                ldmatrix_x4(r0, r1, r2, r3, sb);
                bf[2 * nj2][0]     = r0; bf[2 * nj2][1]     = r1;
                bf[2 * nj2 + 1][0] = r2; bf[2 * nj2 + 1][1] = r3;
            }
#pragma unroll
            for (int nj = 0; nj < 8; nj++) {
                mma_f16(acc[0][nj][0], acc[0][nj][1], acc[0][nj][2], acc[0][nj][3],
                        af[0][0], af[0][1], af[0][2], af[0][3], bf[nj][0], bf[nj][1]);
                mma_f16(acc[1][nj][0], acc[1][nj][1], acc[1][nj][2], acc[1][nj][3],
                        af[1][0], af[1][1], af[1][2], af[1][3], bf[nj][0], bf[nj][1]);
            }
        }
        __syncthreads();
    }

    // ---- epilogue: bias + store (c0,c1 contiguous -> float2) ----
#pragma unroll
    for (int mi = 0; mi < 2; mi++) {
        const int m0 = bm + wm * 32 + mi * 16 + gid;
#pragma unroll
        for (int nj = 0; nj < 8; nj++) {
            const int n = bn + wn * 64 + nj * 8 + 2 * tig;
            const float b0 = bias[n];
            const float b1 = bias[n + 1];
            if (m0 < M) {
                float2 v = make_float2(acc[mi][nj][0] + b0, acc[mi][nj][1] + b1);
                *reinterpret_cast<float2*>(out + (long long)m0 * NOUT + n) = v;
            }
            if (m0 + 8 < M) {
                float2 v = make_float2(acc[mi][nj][2] + b0, acc[mi][nj][3] + b1);
                *reinterpret_cast<float2*>(out + (long long)(m0 + 8) * NOUT + n) = v;
            }
        }
    }
#undef ISSUE_STAGE
}

// ---------------------------------------------------------------------------
// Launch
// Inputs: x_self[f32 B*F], feats[f32 N*F], neigh_idx[B*K], W[f32 512*256], b[f32 256]
// ---------------------------------------------------------------------------
extern "C" void kernel_launch(void* const* d_in, const int* in_sizes, int n_in,
                              void* d_out, int out_size) {
    const float4* xself4 = (const float4*)d_in[0];
    const float4* feats4 = (const float4*)d_in[1];
    const void*   nidx   = d_in[2];
    const float*  W      = (const float*)d_in[3];
    const float*  bias   = (const float*)d_in[4];
    float*        out    = (float*)d_out;

    (void)in_sizes; (void)n_in; (void)out_size;

    // 1) fp32 -> fp16: feature table + x_self (single streaming launch)
    convert_kernel<<<FEATS_BLOCKS + XSELF_BLOCKS, 256>>>(feats4, xself4);

    // 1b) W -> W_t fp16 (transposed)
    {
        dim3 g(2 * FDIM / 32, NOUT / 32);
        convert_W_kernel<<<g, 256>>>(W);
    }

    // 2) gather + mean -> right half of g_h
    gather_mean_kernel<<<BATCH / 8, 256>>>(nidx);

    // 3) fp16 tensor-core GEMM, cp.async pipeline
    dim3 grid((BATCH + BM - 1) / BM, NOUT / BN);
    gemm_f16_pipe_kernel<<<grid, 256>>>(bias, out, BATCH);
}

// round 8
// speedup vs baseline: 2.9714x; 1.2009x over previous
#include <cuda_runtime.h>
#include <cuda_fp16.h>
#include <cstdint>

// Problem constants (fixed by the reference)
#define BATCH   50000
#define KNEI    32
#define FDIM    256     // feature dim; 2F = 512 = GEMM K
#define NNODES  200000
#define NOUT    256

// fp16 copy of the feature table [NNODES, FDIM] (rebuilt every call)
__device__ __half g_feats_h[(size_t)NNODES * FDIM];
// fp16 concatenated GEMM A matrix: [BATCH][512] = [x_self_f16 | x_neigh_f16]
__device__ __half g_h[(size_t)BATCH * 2 * FDIM];
// fp16 transposed weights: W_t[n][k], n in [0,256), k in [0,512)
__device__ __half g_W_t[(size_t)NOUT * 2 * FDIM];

#define FEATS_BLOCKS ((NNODES * FDIM) / (256 * 8))   // 25000
#define XSELF_BLOCKS ((BATCH * FDIM) / (256 * 8))    // 6250

// ---------------------------------------------------------------------------
// Kernel 1: convert feats fp32 -> fp16 table AND x_self fp32 -> fp16 into the
// left half of g_h.  One launch, both pure HBM streaming.
// ---------------------------------------------------------------------------
__global__ void convert_kernel(const float4* __restrict__ feats4,
                               const float4* __restrict__ xself4) {
    if (blockIdx.x < FEATS_BLOCKS) {
        const long long t = (long long)blockIdx.x * 256 + threadIdx.x;
        const float4 a = feats4[2 * t];
        const float4 b = feats4[2 * t + 1];
        __half2 o[4];
        o[0] = __floats2half2_rn(a.x, a.y);
        o[1] = __floats2half2_rn(a.z, a.w);
        o[2] = __floats2half2_rn(b.x, b.y);
        o[3] = __floats2half2_rn(b.z, b.w);
        *reinterpret_cast<uint4*>(g_feats_h + t * 8) = *reinterpret_cast<uint4*>(o);
    } else {
        const long long e = (long long)(blockIdx.x - FEATS_BLOCKS) * 256 + threadIdx.x;
        const float4 a = xself4[2 * e];
        const float4 b = xself4[2 * e + 1];
        __half2 o[4];
        o[0] = __floats2half2_rn(a.x, a.y);
        o[1] = __floats2half2_rn(a.z, a.w);
        o[2] = __floats2half2_rn(b.x, b.y);
        o[3] = __floats2half2_rn(b.z, b.w);
        const long long row = e / 32;          // 32 * 8 halves = 256 per row
        const long long col = (e % 32) * 8;
        *reinterpret_cast<uint4*>(g_h + row * (2 * FDIM) + col) =
            *reinterpret_cast<uint4*>(o);
    }
}

// ---------------------------------------------------------------------------
// Kernel 1b: W [512k][256n] fp32 -> W_t [256n][512k] fp16 (tiled transpose)
// ---------------------------------------------------------------------------
__global__ void convert_W_kernel(const float* __restrict__ W) {
    __shared__ float tile[32][33];
    const int tx = threadIdx.x & 31;
    const int ty = threadIdx.x >> 5;        // 0..7
    const int k0 = blockIdx.x * 32;
    const int n0 = blockIdx.y * 32;
#pragma unroll
    for (int j = 0; j < 4; j++)
        tile[ty + j * 8][tx] = W[(long long)(k0 + ty + j * 8) * NOUT + n0 + tx];
    __syncthreads();
#pragma unroll
    for (int j = 0; j < 4; j++) {
        const int n = ty + j * 8;
        g_W_t[(long long)(n0 + n) * (2 * FDIM) + k0 + tx] =
            __float2half(tile[tx][n]);
    }
}

// ---------------------------------------------------------------------------
// Kernel 2: gather + mean from fp16 table, fp32 accumulate, fp16 out into
// the right half (cols 256..511) of g_h.  8 rows/block, 1 warp per row.
// ---------------------------------------------------------------------------
__global__ void gather_mean_kernel(const void* __restrict__ idx_raw) {
    const int tid  = threadIdx.x;
    const int warp = tid >> 5;
    const int lane = tid & 31;

    int hi_zero = 1;
    if (tid < 128) {
        const uint2 probe = reinterpret_cast<const uint2*>(idx_raw)[tid];
        hi_zero = (probe.y == 0u);
    }
    const int is64 = __syncthreads_and(hi_zero);

    __shared__ int sidx[256];
    const long long flat = (long long)blockIdx.x * 256 + tid;
    int v;
    if (is64) v = (int)reinterpret_cast<const long long*>(idx_raw)[flat];
    else      v = reinterpret_cast<const int*>(idx_raw)[flat];
    sidx[tid] = v;
    __syncthreads();

    const int row = blockIdx.x * 8 + warp;

    float acc[8];
#pragma unroll
    for (int j = 0; j < 8; j++) acc[j] = 0.f;

#pragma unroll
    for (int k = 0; k < KNEI; k++) {
        const long long node = sidx[warp * KNEI + k];
        const uint4 raw = *reinterpret_cast<const uint4*>(
            g_feats_h + node * FDIM + lane * 8);
        const __half2* h = reinterpret_cast<const __half2*>(&raw);
#pragma unroll
        for (int j = 0; j < 4; j++) {
            const float2 f = __half22float2(h[j]);
            acc[2 * j]     += f.x;
            acc[2 * j + 1] += f.y;
        }
    }
    const float s = 1.0f / (float)KNEI;
    __half2 o[4];
#pragma unroll
    for (int j = 0; j < 4; j++)
        o[j] = __floats2half2_rn(acc[2 * j] * s, acc[2 * j + 1] * s);
    *reinterpret_cast<uint4*>(g_h + (long long)row * (2 * FDIM) + FDIM + lane * 8) =
        *reinterpret_cast<uint4*>(o);
}

// ---------------------------------------------------------------------------
// Kernel 3: fp16 tensor-core GEMM, 4-stage cp.async pipeline, high occupancy.
//   out[M,256] = g_h[M,512] @ W_t^T + bias
// BM=128, BN=64, BK=32, STAGES=4 (48KB smem, 4 CTAs/SM).  8 warps:
// 4 in M x 2 in N, warp tile 32x32 -> 32 fp32 accs/thread (regs <= 64).
// A tile [128][32]h, B tile [64][32]h, XOR-16B swizzle
// (off ^ ((off>>7 & 7) << 4)): self-consistent, conflict-free ldmatrix.
// ---------------------------------------------------------------------------
#define BM 128
#define BN 64
#define BK 32
#define STAGES 4
#define A_TILE_B (BM * BK * 2)            // 8192
#define B_TILE_B (BN * BK * 2)            // 4096
#define STAGE_B  (A_TILE_B + B_TILE_B)    // 12288

__device__ __forceinline__ unsigned swz(unsigned off) {
    return off ^ (((off >> 7) & 7u) << 4);
}

__device__ __forceinline__ void mma_f16(float& d0, float& d1, float& d2, float& d3,
                                        unsigned a0, unsigned a1, unsigned a2, unsigned a3,
                                        unsigned b0, unsigned b1) {
    asm volatile(
        "mma.sync.aligned.m16n8k16.row.col.f32.f16.f16.f32 "
        "{%0,%1,%2,%3}, {%4,%5,%6,%7}, {%8,%9}, {%0,%1,%2,%3};"
        : "+f"(d0), "+f"(d1), "+f"(d2), "+f"(d3)
        : "r"(a0), "r"(a1), "r"(a2), "r"(a3), "r"(b0), "r"(b1));
}

__device__ __forceinline__ void ldmatrix_x4(unsigned& r0, unsigned& r1,
                                            unsigned& r2, unsigned& r3,
                                            unsigned saddr) {
    asm volatile("ldmatrix.sync.aligned.m8n8.x4.shared.b16 {%0,%1,%2,%3}, [%4];"
                 : "=r"(r0), "=r"(r1), "=r"(r2), "=r"(r3) : "r"(saddr));
}

__device__ __forceinline__ void cp_async16(unsigned dst, const void* src, int sz) {
    asm volatile("cp.async.cg.shared.global [%0], [%1], 16, %2;\n"
                 :: "r"(dst), "l"(src), "r"(sz));
}
__device__ __forceinline__ void cp_commit() {
    asm volatile("cp.async.commit_group;\n");
}
template <int N>
__device__ __forceinline__ void cp_wait() {
    asm volatile("cp.async.wait_group %0;\n" :: "n"(N));
}

__global__ __launch_bounds__(256, 4)
void gemm_f16_pipe_kernel(const float* __restrict__ bias,
                          float* __restrict__ out,
                          int M) {
    __shared__ __align__(16) char smem[STAGES * STAGE_B];   // 48 KB

    const int bm  = blockIdx.x * BM;
    const int bn  = blockIdx.y * BN;
    const int tid = threadIdx.x;

    const int warp = tid >> 5;
    const int lane = tid & 31;
    const int wm   = warp >> 1;        // 0..3
    const int wn   = warp & 1;         // 0..1
    const int gid  = lane >> 2;        // 0..7
    const int tig  = lane & 3;         // 0..3

    const unsigned sbase = (unsigned)__cvta_generic_to_shared(smem);

    const __half* __restrict__ A  = g_h;
    const __half* __restrict__ Wt = g_W_t;

    // A fragment ldmatrix lane addressing
    const int lm_tile = lane >> 3;
    const int lm_row  = (lane & 7) + (lm_tile & 1) * 8;
    const int lm_koff = (lm_tile >> 1) * 8;
    // B fragment ldmatrix lane addressing (non-trans over [n][k] rows)
    const int bn_row  = ((lane >> 4) & 1) * 8 + (lane & 7);
    const int bk_add  = ((lane >> 3) & 1) * 8;

    float acc[2][4][4];
#pragma unroll
    for (int i = 0; i < 2; i++)
#pragma unroll
        for (int j = 0; j < 4; j++)
#pragma unroll
            for (int q = 0; q < 4; q++) acc[i][j][q] = 0.f;

    // stage s covers k0 = s*BK halves.  Per stage: A = 512 16B-granules
    // (2/thread), B = 256 granules (1/thread).
#define ISSUE_STAGE(s, buf)                                                     \
    {                                                                           \
        const int k0 = (s) * BK;                                                \
        const unsigned abase = sbase + (buf) * STAGE_B;                         \
        const unsigned bbase = abase + A_TILE_B;                                \
        _Pragma("unroll")                                                       \
        for (int i = 0; i < 2; i++) {                                           \
            const int fi = tid + i * 256;                                       \
            const int r  = fi >> 2;                                             \
            const int g  = fi & 3;                                              \
            const unsigned soff = swz((unsigned)(r * 64 + g * 16));             \
            const int m = bm + r;                                               \
            cp_async16(abase + soff,                                            \
                       A + (long long)m * (2 * FDIM) + k0 + g * 8,              \
                       (m < M) ? 16 : 0);                                       \
        }                                                                       \
        {                                                                       \
            const int r = tid >> 2;                                             \
            const int g = tid & 3;                                              \
            const unsigned soff = swz((unsigned)(r * 64 + g * 16));             \
            cp_async16(bbase + soff,                                            \
                       Wt + (long long)(bn + r) * (2 * FDIM) + k0 + g * 8, 16); \
        }                                                                       \
        cp_commit();                                                            \
    }

    // ---- prologue: issue stages 0,1,2 ----
    ISSUE_STAGE(0, 0)
    ISSUE_STAGE(1, 1)
    ISSUE_STAGE(2, 2)

    const int NSTAGE = (2 * FDIM) / BK;   // 16

#pragma unroll 1
    for (int s = 0; s < NSTAGE; s++) {
        if (s < NSTAGE - 2)      cp_wait<2>();
        else if (s == NSTAGE - 2) cp_wait<1>();
        else                      cp_wait<0>();
        __syncthreads();

        // issue stage s+3 into buffer (s+3)%4
        if (s + 3 < NSTAGE) {
            const int nb = (s + 3) % STAGES;
            ISSUE_STAGE(s + 3, nb)
        }

        // compute stage s from buffer s%4
        const unsigned abase = sbase + (s % STAGES) * STAGE_B;
        const unsigned bbase = abase + A_TILE_B;

#pragma unroll
        for (int ks = 0; ks < 2; ks++) {
            const int kk = ks * 16;
            unsigned af[2][4];
#pragma unroll
            for (int mi = 0; mi < 2; mi++) {
                const int r = wm * 32 + mi * 16 + lm_row;
                const unsigned sa = abase + swz((unsigned)(r * 64 + (kk + lm_koff) * 2));
                ldmatrix_x4(af[mi][0], af[mi][1], af[mi][2], af[mi][3], sa);
            }
            unsigned bf[4][2];
#pragma unroll
            for (int nj2 = 0; nj2 < 2; nj2++) {
                const int n = wn * 32 + nj2 * 16 + bn_row;
                const unsigned sb = bbase + swz((unsigned)(n * 64 + (kk + bk_add) * 2));
                unsigned r0, r1, r2, r3;
                ldmatrix_x4(r0, r1, r2, r3, sb);
                bf[2 * nj2][0]     = r0; bf[2 * nj2][1]     = r1;
                bf[2 * nj2 + 1][0] = r2; bf[2 * nj2 + 1][1] = r3;
            }
#pragma unroll
            for (int nj = 0; nj < 4; nj++) {
                mma_f16(acc[0][nj][0], acc[0][nj][1], acc[0][nj][2], acc[0][nj][3],
                        af[0][0], af[0][1], af[0][2], af[0][3], bf[nj][0], bf[nj][1]);
                mma_f16(acc[1][nj][0], acc[1][nj][1], acc[1][nj][2], acc[1][nj][3],
                        af[1][0], af[1][1], af[1][2], af[1][3], bf[nj][0], bf[nj][1]);
            }
        }
        __syncthreads();
    }

    // ---- epilogue: bias + store (c0,c1 contiguous -> float2) ----
#pragma unroll
    for (int mi = 0; mi < 2; mi++) {
        const int m0 = bm + wm * 32 + mi * 16 + gid;
#pragma unroll
        for (int nj = 0; nj < 4; nj++) {
            const int n = bn + wn * 32 + nj * 8 + 2 * tig;
            const float b0 = bias[n];
            const float b1 = bias[n + 1];
            if (m0 < M) {
                float2 v = make_float2(acc[mi][nj][0] + b0, acc[mi][nj][1] + b1);
                *reinterpret_cast<float2*>(out + (long long)m0 * NOUT + n) = v;
            }
            if (m0 + 8 < M) {
                float2 v = make_float2(acc[mi][nj][2] + b0, acc[mi][nj][3] + b1);
                *reinterpret_cast<float2*>(out + (long long)(m0 + 8) * NOUT + n) = v;
            }
        }
    }
#undef ISSUE_STAGE
}

// ---------------------------------------------------------------------------
// Launch
// Inputs: x_self[f32 B*F], feats[f32 N*F], neigh_idx[B*K], W[f32 512*256], b[f32 256]
// ---------------------------------------------------------------------------
extern "C" void kernel_launch(void* const* d_in, const int* in_sizes, int n_in,
                              void* d_out, int out_size) {
    const float4* xself4 = (const float4*)d_in[0];
    const float4* feats4 = (const float4*)d_in[1];
    const void*   nidx   = d_in[2];
    const float*  W      = (const float*)d_in[3];
    const float*  bias   = (const float*)d_in[4];
    float*        out    = (float*)d_out;

    (void)in_sizes; (void)n_in; (void)out_size;

    // 1) fp32 -> fp16: feature table + x_self (single streaming launch)
    convert_kernel<<<FEATS_BLOCKS + XSELF_BLOCKS, 256>>>(feats4, xself4);

    // 1b) W -> W_t fp16 (transposed)
    {
        dim3 g(2 * FDIM / 32, NOUT / 32);
        convert_W_kernel<<<g, 256>>>(W);
    }

    // 2) gather + mean -> right half of g_h
    gather_mean_kernel<<<BATCH / 8, 256>>>(nidx);

    // 3) fp16 tensor-core GEMM, 4-stage cp.async pipeline
    dim3 grid((BATCH + BM - 1) / BM, NOUT / BN);
    gemm_f16_pipe_kernel<<<grid, 256>>>(bias, out, BATCH);
}